// round 3
// baseline (speedup 1.0000x reference)
#include <cuda_runtime.h>
#include <cuda_bf16.h>
#include <math.h>
#include <stdint.h>

#define Bsz 4
#define Nn 1024
#define Cc 512
#define Hh 8
#define DH 64
#define BH 32
#define INNER 512
#define Ff 160    // 64 (E) + 64 (S) + 32 (H)
#define FPAD 192  // gmem row padding (16B aligned rows)
#define LDS_A 168 // smem row stride in bf16 elems (conflict-free ldmatrix)

// ---- scratch (static device allocations; no runtime alloc) ----
__device__ float g_Q[BH * Nn * DH];
__device__ float g_K[BH * Nn * DH];
__device__ float g_V[BH * Nn * DH];
__device__ __nv_bfloat16 g_FQh[(size_t)BH * Nn * FPAD];
__device__ __nv_bfloat16 g_FQl[(size_t)BH * Nn * FPAD];
__device__ __nv_bfloat16 g_FKh[(size_t)BH * Nn * FPAD];
__device__ __nv_bfloat16 g_FKl[(size_t)BH * Nn * FPAD];
__device__ float g_QA[BH * Nn];
__device__ float g_QU[BH * Nn];
__device__ float g_KB[BH * Nn];
__device__ float g_KV[BH * Nn];
__device__ float g_S[(size_t)BH * Nn * Nn];  // scores -> probs (128 MB)
__device__ float g_O[Bsz * Nn * INNER];

__device__ __forceinline__ float softplusf(float x) {
    return (x > 20.f) ? x : log1pf(expf(x));
}
__device__ __forceinline__ float fast_sqrt(float x) {
    float r; asm("sqrt.approx.f32 %0, %1;" : "=f"(r) : "f"(x)); return r;
}
__device__ __forceinline__ float fast_rcp(float x) {
    float r; asm("rcp.approx.f32 %0, %1;" : "=f"(r) : "f"(x)); return r;
}
__device__ __forceinline__ uint32_t smem_u32(const void* p) {
    uint32_t a;
    asm("{ .reg .u64 tmp; cvta.to.shared.u64 tmp, %1; cvt.u32.u64 %0, tmp; }" : "=r"(a) : "l"(p));
    return a;
}
__device__ __forceinline__ void ldsm_x4(uint32_t& r0, uint32_t& r1, uint32_t& r2, uint32_t& r3, uint32_t addr) {
    asm volatile("ldmatrix.sync.aligned.m8n8.x4.shared.b16 {%0,%1,%2,%3}, [%4];"
                 : "=r"(r0), "=r"(r1), "=r"(r2), "=r"(r3) : "r"(addr));
}
__device__ __forceinline__ void ldsm_x2(uint32_t& r0, uint32_t& r1, uint32_t addr) {
    asm volatile("ldmatrix.sync.aligned.m8n8.x2.shared.b16 {%0,%1}, [%2];"
                 : "=r"(r0), "=r"(r1) : "r"(addr));
}
__device__ __forceinline__ void mma_bf16(float* d, uint32_t a0, uint32_t a1, uint32_t a2, uint32_t a3,
                                         uint32_t b0, uint32_t b1) {
    asm volatile("mma.sync.aligned.m16n8k16.row.col.f32.bf16.bf16.f32 "
                 "{%0,%1,%2,%3}, {%4,%5,%6,%7}, {%8,%9}, {%0,%1,%2,%3};"
                 : "+f"(d[0]), "+f"(d[1]), "+f"(d[2]), "+f"(d[3])
                 : "r"(a0), "r"(a1), "r"(a2), "r"(a3), "r"(b0), "r"(b1));
}

// ============================================================
// K1: qkv = x @ w_qkv^T, scattered into per-head Q/K/V layout
// ============================================================
__global__ __launch_bounds__(256) void k_qkv(const float* __restrict__ x,
                                             const float* __restrict__ w) {
    __shared__ float As[16][65];
    __shared__ float Bs[16][65];
    int tid = threadIdx.x;
    int ty = tid >> 4, tx = tid & 15;
    const float* Abase = x + (size_t)(blockIdx.y * 64) * Cc;
    const float* Bbase = w + (size_t)(blockIdx.x * 64) * Cc;
    float acc[4][4] = {};
    for (int k0 = 0; k0 < Cc; k0 += 16) {
#pragma unroll
        for (int i = 0; i < 4; i++) {
            int f = tid + 256 * i;
            int mm = f >> 4, kk = f & 15;
            As[kk][mm] = Abase[(size_t)mm * Cc + k0 + kk];
            Bs[kk][mm] = Bbase[(size_t)mm * Cc + k0 + kk];
        }
        __syncthreads();
#pragma unroll
        for (int kk = 0; kk < 16; kk++) {
            float a[4], b[4];
#pragma unroll
            for (int i = 0; i < 4; i++) { a[i] = As[kk][ty * 4 + i]; b[i] = Bs[kk][tx * 4 + i]; }
#pragma unroll
            for (int i = 0; i < 4; i++)
#pragma unroll
                for (int j = 0; j < 4; j++) acc[i][j] += a[i] * b[j];
        }
        __syncthreads();
    }
    int m0 = blockIdx.y * 64 + ty * 4;
    int n0 = blockIdx.x * 64 + tx * 4;
#pragma unroll
    for (int i = 0; i < 4; i++)
#pragma unroll
        for (int j = 0; j < 4; j++) {
            int m = m0 + i, jc = n0 + j;
            int b = m / Nn, n = m % Nn;
            int part = jc / INNER, r = jc % INNER;
            int h = r / DH, d = r % DH;
            float* dst = (part == 0) ? g_Q : ((part == 1) ? g_K : g_V);
            dst[((size_t)(b * Hh + h) * Nn + n) * DH + d] = acc[i][j];
        }
}

// ============================================================
// K2: per-token metric embeddings -> bf16 hi/lo features + norms
// ============================================================
__global__ __launch_bounds__(256) void k_embed(const float* __restrict__ we, const float* __restrict__ be,
                                               const float* __restrict__ ws, const float* __restrict__ bs,
                                               const float* __restrict__ wh, const float* __restrict__ bhh) {
    __shared__ float W[Ff][65];
    __shared__ float bias[Ff];
    __shared__ float qr[4][64];
    __shared__ float raw[4][Ff];
    int tid = threadIdx.x;
    for (int i = tid; i < 64 * 64; i += 256) { W[i / 64][i % 64] = we[i]; W[64 + i / 64][i % 64] = ws[i]; }
    for (int i = tid; i < 32 * 64; i += 256) W[128 + i / 64][i % 64] = wh[i];
    for (int i = tid; i < Ff; i += 256) bias[i] = (i < 64) ? be[i] : ((i < 128) ? bs[i - 64] : bhh[i - 128]);
    const float* src = (blockIdx.y == 0) ? g_Q : g_K;
    int tok0 = blockIdx.x * 4;
    for (int i = tid; i < 4 * 64; i += 256) qr[i / 64][i % 64] = src[(size_t)(tok0 + i / 64) * 64 + (i % 64)];
    __syncthreads();
    for (int i = tid; i < 4 * Ff; i += 256) {
        int tt = i / Ff, j = i % Ff;
        float s = bias[j];
#pragma unroll 8
        for (int c = 0; c < 64; c++) s += qr[tt][c] * W[j][c];
        raw[tt][j] = s;
    }
    __syncthreads();
    int w = tid >> 5, lane = tid & 31;
    if (w < 4) {
        int tt = w;
        float an = 0.f, sn = 0.f, un = 0.f;
        for (int j = lane; j < 64; j += 32) { float v = raw[tt][j]; an += v * v; }
        for (int j = 64 + lane; j < 128; j += 32) { float v = raw[tt][j]; sn += v * v; }
        {
            int j = 128 + lane;
            float th = tanhf(raw[tt][j]);
            raw[tt][j] = th;
            un += th * th;
        }
#pragma unroll
        for (int o = 16; o; o >>= 1) {
            an += __shfl_xor_sync(0xffffffffu, an, o);
            sn += __shfl_xor_sync(0xffffffffu, sn, o);
            un += __shfl_xor_sync(0xffffffffu, un, o);
        }
        float inv = 1.f / fmaxf(sqrtf(sn), 1e-12f);
        __syncwarp();
        __nv_bfloat16* Fh = (blockIdx.y == 0) ? g_FQh : g_FKh;
        __nv_bfloat16* Fl = (blockIdx.y == 0) ? g_FQl : g_FKl;
        int tok = tok0 + tt;
        for (int j = lane; j < Ff; j += 32) {
            float v = raw[tt][j];
            if (j >= 64 && j < 128) v *= inv;
            __nv_bfloat16 hi = __float2bfloat16(v);
            float lo = v - __bfloat162float(hi);
            Fh[(size_t)tok * FPAD + j] = hi;
            Fl[(size_t)tok * FPAD + j] = __float2bfloat16(lo);
        }
        if (lane == 0) {
            if (blockIdx.y == 0) { g_QA[tok] = an; g_QU[tok] = un; }
            else                 { g_KB[tok] = an; g_KV[tok] = un; }
        }
    }
}

// ============================================================
// K3: HMMA bf16 split GEMM (3 passes) + fast distance epilogue
// CTA tile: 128 rows x 64 cols. 256 threads / 8 warps, 32x32 per warp.
// ============================================================
#define OFF_AH 0
#define OFF_AL (128 * LDS_A * 2)
#define OFF_BH (2 * 128 * LDS_A * 2)
#define OFF_BL (2 * 128 * LDS_A * 2 + 64 * LDS_A * 2)
#define SCORE_SMEM (2 * 128 * LDS_A * 2 + 2 * 64 * LDS_A * 2)  // 129024 B

__global__ __launch_bounds__(256, 1) void k_score_mma(const float* __restrict__ alpha,
                                                      const float* __restrict__ beta,
                                                      const float* __restrict__ gamma,
                                                      const float* __restrict__ temp) {
    extern __shared__ char dyn[];
    __shared__ float sAN[128], sUN[128], sBN[64], sVN[64];

    int tid = threadIdx.x;
    int wid = tid >> 5, lane = tid & 31;
    int bh = blockIdx.z;
    int row0 = blockIdx.y * 128, col0 = blockIdx.x * 64;

    uint32_t sb = smem_u32(dyn);

    // norms into shared
    if (tid < 128) { sAN[tid] = g_QA[bh * Nn + row0 + tid]; sUN[tid] = g_QU[bh * Nn + row0 + tid]; }
    else { int t = tid - 128; if (t < 64) { sBN[t] = g_KB[bh * Nn + col0 + t]; sVN[t] = g_KV[bh * Nn + col0 + t]; } }

    // stage tiles: 160 bf16 per row = 20 uint4 per row
    {
        const uint4* sAh = (const uint4*)(g_FQh + ((size_t)bh * Nn + row0) * FPAD);
        const uint4* sAl = (const uint4*)(g_FQl + ((size_t)bh * Nn + row0) * FPAD);
        const uint4* sBh = (const uint4*)(g_FKh + ((size_t)bh * Nn + col0) * FPAD);
        const uint4* sBl = (const uint4*)(g_FKl + ((size_t)bh * Nn + col0) * FPAD);
        // FPAD=192 bf16 = 24 uint4 per gmem row
        for (int idx = tid; idx < 128 * 20; idx += 256) {
            int r = idx / 20, c = idx % 20;
            uint4 vh = sAh[r * 24 + c];
            uint4 vl = sAl[r * 24 + c];
            *(uint4*)(dyn + OFF_AH + (r * LDS_A + c * 8) * 2) = vh;
            *(uint4*)(dyn + OFF_AL + (r * LDS_A + c * 8) * 2) = vl;
        }
        for (int idx = tid; idx < 64 * 20; idx += 256) {
            int r = idx / 20, c = idx % 20;
            uint4 vh = sBh[r * 24 + c];
            uint4 vl = sBl[r * 24 + c];
            *(uint4*)(dyn + OFF_BH + (r * LDS_A + c * 8) * 2) = vh;
            *(uint4*)(dyn + OFF_BL + (r * LDS_A + c * 8) * 2) = vl;
        }
    }
    __syncthreads();

    int wr0 = (wid & 3) * 32, wc0 = (wid >> 2) * 32;

    float acc[3][8][4];
#pragma unroll
    for (int g = 0; g < 3; g++)
#pragma unroll
        for (int t = 0; t < 8; t++)
#pragma unroll
            for (int e = 0; e < 4; e++) acc[g][t][e] = 0.f;

    // fragment smem addresses (lane-dependent parts precomputed)
    uint32_t aAddrBase = sb + ((wr0 + (lane & 15)) * LDS_A + (lane >> 4) * 8) * 2;
    uint32_t bAddrBase = sb + ((wc0 + (lane & 7)) * LDS_A + ((lane >> 3) & 1) * 8) * 2;

#pragma unroll
    for (int pz = 0; pz < 3; pz++) {
        uint32_t aOff = (pz == 2) ? OFF_AL : OFF_AH;
        uint32_t bOff = (pz == 1) ? OFF_BL : OFF_BH;
#pragma unroll
        for (int kc = 0; kc < 10; kc++) {
            const int grp = (kc < 4) ? 0 : ((kc < 8) ? 1 : 2);
            uint32_t a0[2], a1[2], a2[2], a3[2];
#pragma unroll
            for (int mt = 0; mt < 2; mt++)
                ldsm_x4(a0[mt], a1[mt], a2[mt], a3[mt],
                        aAddrBase + aOff + (mt * 16 * LDS_A + kc * 16) * 2);
            uint32_t b0[4], b1[4];
#pragma unroll
            for (int nt = 0; nt < 4; nt++)
                ldsm_x2(b0[nt], b1[nt],
                        bAddrBase + bOff + (nt * 8 * LDS_A + kc * 16) * 2);
#pragma unroll
            for (int mt = 0; mt < 2; mt++)
#pragma unroll
                for (int nt = 0; nt < 4; nt++)
                    mma_bf16(acc[grp][mt * 4 + nt], a0[mt], a1[mt], a2[mt], a3[mt], b0[nt], b1[nt]);
        }
    }

    // epilogue
    float cE = softplusf(alpha[0]);
    float cS = softplusf(beta[0]);
    float cH = softplusf(gamma[0]);
    float negInvT = -fast_rcp(softplusf(temp[0]));

    float* Sbh = g_S + (size_t)bh * Nn * Nn;
#pragma unroll
    for (int mt = 0; mt < 2; mt++) {
#pragma unroll
        for (int mo = 0; mo < 2; mo++) {
            int r = wr0 + mt * 16 + mo * 8 + (lane >> 2);
            float an = sAN[r], un = sUN[r];
            float one_m_un = 1.f - un;
            float* Srow = Sbh + (size_t)(row0 + r) * Nn + col0;
#pragma unroll
            for (int nt = 0; nt < 4; nt++) {
                int c = wc0 + nt * 8 + (lane & 3) * 2;
                float2 o;
#pragma unroll
                for (int e = 0; e < 2; e++) {
                    float bn = sBN[c + e], vn = sVN[c + e];
                    float ev = acc[0][mt * 4 + nt][mo * 2 + e];
                    float sv = acc[1][mt * 4 + nt][mo * 2 + e];
                    float hv = acc[2][mt * 4 + nt][mo * 2 + e];
                    float dE = fast_sqrt(fmaxf(an + bn - 2.f * ev, 1e-12f));
                    float x = fminf(fmaxf(sv, -1.f + 1e-6f), 1.f - 1e-6f);
                    float ax = fabsf(x);
                    float poly = fmaf(ax, fmaf(ax, fmaf(ax, -0.0187293f, 0.0742610f), -0.2121144f), 1.5707288f);
                    float rr = fast_sqrt(1.f - ax) * poly;
                    float dS = (x >= 0.f) ? rr : (3.14159265358979f - rr);
                    float dns = fmaxf(un + vn - 2.f * hv, 0.f);
                    float denom = one_m_un * (1.f - vn) + 1e-8f;
                    float t = fmaxf(2.f * dns * fast_rcp(denom), 1e-6f);
                    float sh = fast_sqrt(t * (t + 2.f));
                    float dHp = __logf(1.f + t + sh);
                    float sc = negInvT * (cE * dE + cS * dS + cH * dHp);
                    if (e == 0) o.x = sc; else o.y = sc;
                }
                *(float2*)(Srow + c) = o;
            }
        }
    }
}

// ============================================================
// K4: row softmax in place over g_S
// ============================================================
__global__ __launch_bounds__(256) void k_softmax() {
    __shared__ float red[8];
    size_t base = (size_t)blockIdx.x * Nn;
    int tid = threadIdx.x;
    float v[4];
#pragma unroll
    for (int i = 0; i < 4; i++) v[i] = g_S[base + tid + 256 * i];
    float m = fmaxf(fmaxf(v[0], v[1]), fmaxf(v[2], v[3]));
#pragma unroll
    for (int o = 16; o; o >>= 1) m = fmaxf(m, __shfl_xor_sync(0xffffffffu, m, o));
    if ((tid & 31) == 0) red[tid >> 5] = m;
    __syncthreads();
    float M = red[0];
#pragma unroll
    for (int i = 1; i < 8; i++) M = fmaxf(M, red[i]);
    float s = 0.f;
#pragma unroll
    for (int i = 0; i < 4; i++) { v[i] = __expf(v[i] - M); s += v[i]; }
#pragma unroll
    for (int o = 16; o; o >>= 1) s += __shfl_xor_sync(0xffffffffu, s, o);
    __syncthreads();
    if ((tid & 31) == 0) red[tid >> 5] = s;
    __syncthreads();
    float S = 0.f;
#pragma unroll
    for (int i = 0; i < 8; i++) S += red[i];
    float inv = 1.f / S;
#pragma unroll
    for (int i = 0; i < 4; i++) g_S[base + tid + 256 * i] = v[i] * inv;
}

// ============================================================
// K5: out = attn @ V per head
// ============================================================
__global__ __launch_bounds__(256) void k_av() {
    __shared__ float As[16][65];
    __shared__ float Bs[16][64];
    int bh = blockIdx.y;
    int row0 = blockIdx.x * 64;
    int tid = threadIdx.x, ty = tid >> 4, tx = tid & 15;
    const float* Abase = g_S + (size_t)bh * Nn * Nn + (size_t)row0 * Nn;
    const float* Vbase = g_V + (size_t)bh * Nn * DH;
    float acc[4][4] = {};
    for (int k0 = 0; k0 < Nn; k0 += 16) {
#pragma unroll
        for (int i = 0; i < 4; i++) {
            int f = tid + 256 * i;
            int mm = f >> 4, kk = f & 15;
            As[kk][mm] = Abase[(size_t)mm * Nn + k0 + kk];
        }
#pragma unroll
        for (int i = 0; i < 4; i++) {
            int f = tid + 256 * i;
            int kk = f >> 6, nn2 = f & 63;
            Bs[kk][nn2] = Vbase[(size_t)(k0 + kk) * DH + nn2];
        }
        __syncthreads();
#pragma unroll
        for (int kk = 0; kk < 16; kk++) {
            float a[4], b[4];
#pragma unroll
            for (int i = 0; i < 4; i++) { a[i] = As[kk][ty * 4 + i]; b[i] = Bs[kk][tx * 4 + i]; }
#pragma unroll
            for (int i = 0; i < 4; i++)
#pragma unroll
                for (int j = 0; j < 4; j++) acc[i][j] += a[i] * b[j];
        }
        __syncthreads();
    }
    int b = bh / Hh, h = bh % Hh;
#pragma unroll
    for (int i = 0; i < 4; i++) {
        int tok = row0 + ty * 4 + i;
#pragma unroll
        for (int j = 0; j < 4; j++) {
            int d = tx * 4 + j;
            g_O[((size_t)(b * Nn + tok)) * INNER + h * DH + d] = acc[i][j];
        }
    }
}

// ============================================================
// K6: final projection
// ============================================================
__global__ __launch_bounds__(256) void k_proj(const float* __restrict__ wp,
                                              const float* __restrict__ bp,
                                              float* __restrict__ out) {
    __shared__ float As[16][65];
    __shared__ float Bs[16][65];
    int tid = threadIdx.x, ty = tid >> 4, tx = tid & 15;
    const float* Abase = g_O + (size_t)(blockIdx.y * 64) * INNER;
    const float* Bbase = wp + (size_t)(blockIdx.x * 64) * INNER;
    float acc[4][4] = {};
    for (int k0 = 0; k0 < INNER; k0 += 16) {
#pragma unroll
        for (int i = 0; i < 4; i++) {
            int f = tid + 256 * i;
            int mm = f >> 4, kk = f & 15;
            As[kk][mm] = Abase[(size_t)mm * INNER + k0 + kk];
            Bs[kk][mm] = Bbase[(size_t)mm * INNER + k0 + kk];
        }
        __syncthreads();
#pragma unroll
        for (int kk = 0; kk < 16; kk++) {
            float a[4], b[4];
#pragma unroll
            for (int i = 0; i < 4; i++) { a[i] = As[kk][ty * 4 + i]; b[i] = Bs[kk][tx * 4 + i]; }
#pragma unroll
            for (int i = 0; i < 4; i++)
#pragma unroll
                for (int j = 0; j < 4; j++) acc[i][j] += a[i] * b[j];
        }
        __syncthreads();
    }
    int m0 = blockIdx.y * 64 + ty * 4;
    int n0 = blockIdx.x * 64 + tx * 4;
#pragma unroll
    for (int i = 0; i < 4; i++)
#pragma unroll
        for (int j = 0; j < 4; j++)
            out[(size_t)(m0 + i) * Cc + n0 + j] = acc[i][j] + bp[n0 + j];
}

extern "C" void kernel_launch(void* const* d_in, const int* in_sizes, int n_in,
                              void* d_out, int out_size) {
    const float* x      = (const float*)d_in[0];
    const float* w_qkv  = (const float*)d_in[1];
    const float* w_proj = (const float*)d_in[2];
    const float* b_proj = (const float*)d_in[3];
    const float* w_e    = (const float*)d_in[4];
    const float* b_e    = (const float*)d_in[5];
    const float* w_s    = (const float*)d_in[6];
    const float* b_s    = (const float*)d_in[7];
    const float* w_h    = (const float*)d_in[8];
    const float* b_h    = (const float*)d_in[9];
    const float* alpha  = (const float*)d_in[10];
    const float* beta   = (const float*)d_in[11];
    const float* gamma  = (const float*)d_in[12];
    const float* temp   = (const float*)d_in[13];
    float* out = (float*)d_out;

    cudaFuncSetAttribute(k_score_mma, cudaFuncAttributeMaxDynamicSharedMemorySize, SCORE_SMEM);

    k_qkv<<<dim3(24, 64), 256>>>(x, w_qkv);
    k_embed<<<dim3(BH * Nn / 4, 2), 256>>>(w_e, b_e, w_s, b_s, w_h, b_h);
    k_score_mma<<<dim3(16, 8, BH), 256, SCORE_SMEM>>>(alpha, beta, gamma, temp);
    k_softmax<<<BH * Nn, 256>>>();
    k_av<<<dim3(16, BH), 256>>>();
    k_proj<<<dim3(8, 64), 256>>>(w_proj, b_proj, out);
}

// round 4
// speedup vs baseline: 1.6291x; 1.6291x over previous
#include <cuda_runtime.h>
#include <cuda_bf16.h>
#include <math.h>
#include <stdint.h>

#define Bsz 4
#define Nn 1024
#define Cc 512
#define Hh 8
#define DH 64
#define BH 32
#define INNER 512
#define Ff 160   // 64 (E) + 64 (S) + 32 (H)
#define LDP 68   // smem row padding (float4-aligned rows, bank-shifted)

// ---- scratch (static device allocations; no runtime alloc) ----
__device__ float g_Q[BH * Nn * DH];
__device__ float g_K[BH * Nn * DH];
__device__ float g_V[BH * Nn * DH];
__device__ float g_FQ[BH * Nn * Ff];
__device__ float g_FK[BH * Nn * Ff];
__device__ float g_QA[BH * Nn];   // |eq|^2 per query token
__device__ float g_QU[BH * Nn];   // |tanh(hq)|^2 per query token
__device__ float g_KB[BH * Nn];   // |ek|^2
__device__ float g_KV[BH * Nn];   // |tanh(hk)|^2
__device__ float g_S[(size_t)BH * Nn * Nn];  // scores -> probs (128 MB)
__device__ float g_O[Bsz * Nn * INNER];

__device__ __forceinline__ float softplusf(float x) {
    return (x > 20.f) ? x : log1pf(expf(x));
}
__device__ __forceinline__ float fast_sqrt(float x) {
    float r; asm("sqrt.approx.f32 %0, %1;" : "=f"(r) : "f"(x)); return r;
}
__device__ __forceinline__ float fast_rcp(float x) {
    float r; asm("rcp.approx.f32 %0, %1;" : "=f"(r) : "f"(x)); return r;
}

// ============================================================
// K1: qkv = x @ w_qkv^T, scattered into per-head Q/K/V layout
// ============================================================
__global__ __launch_bounds__(256) void k_qkv(const float* __restrict__ x,
                                             const float* __restrict__ w) {
    __shared__ float As[16][LDP];
    __shared__ float Bs[16][LDP];
    int tid = threadIdx.x;
    int ty = tid >> 4, tx = tid & 15;
    const float* Abase = x + (size_t)(blockIdx.y * 64) * Cc;
    const float* Bbase = w + (size_t)(blockIdx.x * 64) * Cc;
    float acc[4][4] = {};
    for (int k0 = 0; k0 < Cc; k0 += 16) {
#pragma unroll
        for (int i = 0; i < 4; i++) {
            int f = tid + 256 * i;
            int mm = f >> 4, kk = f & 15;
            As[kk][mm] = Abase[(size_t)mm * Cc + k0 + kk];
            Bs[kk][mm] = Bbase[(size_t)mm * Cc + k0 + kk];
        }
        __syncthreads();
#pragma unroll
        for (int kk = 0; kk < 16; kk++) {
            float4 a = *(const float4*)&As[kk][ty * 4];
            float4 b = *(const float4*)&Bs[kk][tx * 4];
            acc[0][0] += a.x * b.x; acc[0][1] += a.x * b.y; acc[0][2] += a.x * b.z; acc[0][3] += a.x * b.w;
            acc[1][0] += a.y * b.x; acc[1][1] += a.y * b.y; acc[1][2] += a.y * b.z; acc[1][3] += a.y * b.w;
            acc[2][0] += a.z * b.x; acc[2][1] += a.z * b.y; acc[2][2] += a.z * b.z; acc[2][3] += a.z * b.w;
            acc[3][0] += a.w * b.x; acc[3][1] += a.w * b.y; acc[3][2] += a.w * b.z; acc[3][3] += a.w * b.w;
        }
        __syncthreads();
    }
    int m0 = blockIdx.y * 64 + ty * 4;
    int n0 = blockIdx.x * 64 + tx * 4;
#pragma unroll
    for (int i = 0; i < 4; i++)
#pragma unroll
        for (int j = 0; j < 4; j++) {
            int m = m0 + i, jc = n0 + j;
            int b = m / Nn, n = m % Nn;
            int part = jc / INNER, r = jc % INNER;
            int h = r / DH, d = r % DH;
            float* dst = (part == 0) ? g_Q : ((part == 1) ? g_K : g_V);
            dst[((size_t)(b * Hh + h) * Nn + n) * DH + d] = acc[i][j];
        }
}

// ============================================================
// K2: per-token metric embeddings -> packed feature rows + norm scalars
// ============================================================
__global__ __launch_bounds__(256) void k_embed(const float* __restrict__ we, const float* __restrict__ be,
                                               const float* __restrict__ ws, const float* __restrict__ bs,
                                               const float* __restrict__ wh, const float* __restrict__ bhh) {
    __shared__ float W[Ff][65];
    __shared__ float bias[Ff];
    __shared__ float qr[4][64];
    __shared__ float raw[4][Ff];
    int tid = threadIdx.x;
    for (int i = tid; i < 64 * 64; i += 256) { W[i / 64][i % 64] = we[i]; W[64 + i / 64][i % 64] = ws[i]; }
    for (int i = tid; i < 32 * 64; i += 256) W[128 + i / 64][i % 64] = wh[i];
    for (int i = tid; i < Ff; i += 256) bias[i] = (i < 64) ? be[i] : ((i < 128) ? bs[i - 64] : bhh[i - 128]);
    const float* src = (blockIdx.y == 0) ? g_Q : g_K;
    int tok0 = blockIdx.x * 4;
    for (int i = tid; i < 4 * 64; i += 256) qr[i / 64][i % 64] = src[(size_t)(tok0 + i / 64) * 64 + (i % 64)];
    __syncthreads();
    for (int i = tid; i < 4 * Ff; i += 256) {
        int tt = i / Ff, j = i % Ff;
        float s = bias[j];
#pragma unroll 8
        for (int c = 0; c < 64; c++) s += qr[tt][c] * W[j][c];
        raw[tt][j] = s;
    }
    __syncthreads();
    int w = tid >> 5, lane = tid & 31;
    if (w < 4) {
        int tt = w;
        float an = 0.f, sn = 0.f, un = 0.f;
        for (int j = lane; j < 64; j += 32) { float v = raw[tt][j]; an += v * v; }
        for (int j = 64 + lane; j < 128; j += 32) { float v = raw[tt][j]; sn += v * v; }
        {
            int j = 128 + lane;
            float th = tanhf(raw[tt][j]);
            raw[tt][j] = th;
            un += th * th;
        }
#pragma unroll
        for (int o = 16; o; o >>= 1) {
            an += __shfl_xor_sync(0xffffffffu, an, o);
            sn += __shfl_xor_sync(0xffffffffu, sn, o);
            un += __shfl_xor_sync(0xffffffffu, un, o);
        }
        float inv = 1.f / fmaxf(sqrtf(sn), 1e-12f);
        __syncwarp();
        float* Fdst = (blockIdx.y == 0) ? g_FQ : g_FK;
        int tok = tok0 + tt;
        for (int j = lane; j < Ff; j += 32) {
            float v = raw[tt][j];
            if (j >= 64 && j < 128) v *= inv;
            Fdst[(size_t)tok * Ff + j] = v;
        }
        if (lane == 0) {
            if (blockIdx.y == 0) { g_QA[tok] = an; g_QU[tok] = un; }
            else                 { g_KB[tok] = an; g_KV[tok] = un; }
        }
    }
}

// ============================================================
// K3: combined-feature GEMM (K=160, three accumulator groups)
// + fast distance/score epilogue. Output: g_S scores.
// ============================================================
#define GEMM_STEP(ACC)                                                          \
    _Pragma("unroll")                                                           \
    for (int kk = 0; kk < 16; kk++) {                                           \
        float4 a = *(const float4*)&As[kk][ty * 4];                             \
        float4 b = *(const float4*)&Bs[kk][tx * 4];                             \
        ACC[0][0] += a.x * b.x; ACC[0][1] += a.x * b.y; ACC[0][2] += a.x * b.z; ACC[0][3] += a.x * b.w; \
        ACC[1][0] += a.y * b.x; ACC[1][1] += a.y * b.y; ACC[1][2] += a.y * b.z; ACC[1][3] += a.y * b.w; \
        ACC[2][0] += a.z * b.x; ACC[2][1] += a.z * b.y; ACC[2][2] += a.z * b.z; ACC[2][3] += a.z * b.w; \
        ACC[3][0] += a.w * b.x; ACC[3][1] += a.w * b.y; ACC[3][2] += a.w * b.z; ACC[3][3] += a.w * b.w; \
    }

__global__ __launch_bounds__(256) void k_score(const float* __restrict__ alpha,
                                               const float* __restrict__ beta,
                                               const float* __restrict__ gamma,
                                               const float* __restrict__ temp) {
    __shared__ float As[16][LDP];
    __shared__ float Bs[16][LDP];
    __shared__ float sAN[64], sUN[64], sBN[64], sVN[64];
    int bh = blockIdx.z;
    int row0 = blockIdx.y * 64, col0 = blockIdx.x * 64;
    int tid = threadIdx.x, ty = tid >> 4, tx = tid & 15;
    const float* Abase = g_FQ + ((size_t)bh * Nn + row0) * Ff;
    const float* Bbase = g_FK + ((size_t)bh * Nn + col0) * Ff;
    if (tid < 64)       { sAN[tid] = g_QA[bh * Nn + row0 + tid]; sUN[tid] = g_QU[bh * Nn + row0 + tid]; }
    else if (tid < 128) { int t = tid - 64; sBN[t] = g_KB[bh * Nn + col0 + t]; sVN[t] = g_KV[bh * Nn + col0 + t]; }
    float accE[4][4] = {}, accS[4][4] = {}, accH[4][4] = {};
    for (int kt = 0; kt < 10; ++kt) {
        int k0 = kt * 16;
#pragma unroll
        for (int i = 0; i < 4; i++) {
            int f = tid + 256 * i;
            int mm = f >> 4, kk = f & 15;
            As[kk][mm] = Abase[(size_t)mm * Ff + k0 + kk];
            Bs[kk][mm] = Bbase[(size_t)mm * Ff + k0 + kk];
        }
        __syncthreads();
        if (kt < 4)      { GEMM_STEP(accE) }
        else if (kt < 8) { GEMM_STEP(accS) }
        else             { GEMM_STEP(accH) }
        __syncthreads();
    }
    float cE = softplusf(alpha[0]);
    float cS = softplusf(beta[0]);
    float cH = softplusf(gamma[0]);
    float negInvT = -1.f / softplusf(temp[0]);
    float* Sbase = g_S + (size_t)bh * Nn * Nn;
#pragma unroll
    for (int i = 0; i < 4; i++) {
        int r = row0 + ty * 4 + i;
        float an = sAN[ty * 4 + i], un = sUN[ty * 4 + i];
        float one_m_un = 1.f - un;
        float4 o;
        float* op = (float*)&o;
#pragma unroll
        for (int j = 0; j < 4; j++) {
            int cidx = tx * 4 + j;
            float bn = sBN[cidx], vn = sVN[cidx];
            // Euclidean
            float dE = fast_sqrt(fmaxf(an + bn - 2.f * accE[i][j], 1e-12f));
            // spherical: fast acos (A&S 4.4.45, |err| < 6.8e-5)
            float x = fminf(fmaxf(accS[i][j], -1.f + 1e-6f), 1.f - 1e-6f);
            float ax = fabsf(x);
            float poly = fmaf(ax, fmaf(ax, fmaf(ax, -0.0187293f, 0.0742610f), -0.2121144f), 1.5707288f);
            float rr = fast_sqrt(1.f - ax) * poly;
            float dS = (x >= 0.f) ? rr : (3.14159265358979f - rr);
            // hyperbolic: acosh(1+t) = log(1 + t + sqrt(t*(t+2)))
            float dns = fmaxf(un + vn - 2.f * accH[i][j], 0.f);
            float denom = one_m_un * (1.f - vn) + 1e-8f;
            float t = fmaxf(2.f * dns * fast_rcp(denom), 1e-6f);
            float sh = fast_sqrt(t * (t + 2.f));
            float dHp = __logf(1.f + t + sh);
            op[j] = negInvT * (cE * dE + cS * dS + cH * dHp);
        }
        *(float4*)&Sbase[(size_t)r * Nn + col0 + tx * 4] = o;
    }
}

// ============================================================
// K4: row softmax in place over g_S
// ============================================================
__global__ __launch_bounds__(256) void k_softmax() {
    __shared__ float red[8];
    size_t base = (size_t)blockIdx.x * Nn;
    int tid = threadIdx.x;
    float v[4];
#pragma unroll
    for (int i = 0; i < 4; i++) v[i] = g_S[base + tid + 256 * i];
    float m = fmaxf(fmaxf(v[0], v[1]), fmaxf(v[2], v[3]));
#pragma unroll
    for (int o = 16; o; o >>= 1) m = fmaxf(m, __shfl_xor_sync(0xffffffffu, m, o));
    if ((tid & 31) == 0) red[tid >> 5] = m;
    __syncthreads();
    float M = red[0];
#pragma unroll
    for (int i = 1; i < 8; i++) M = fmaxf(M, red[i]);
    float s = 0.f;
#pragma unroll
    for (int i = 0; i < 4; i++) { v[i] = __expf(v[i] - M); s += v[i]; }
#pragma unroll
    for (int o = 16; o; o >>= 1) s += __shfl_xor_sync(0xffffffffu, s, o);
    __syncthreads();
    if ((tid & 31) == 0) red[tid >> 5] = s;
    __syncthreads();
    float S = 0.f;
#pragma unroll
    for (int i = 0; i < 8; i++) S += red[i];
    float inv = 1.f / S;
#pragma unroll
    for (int i = 0; i < 4; i++) g_S[base + tid + 256 * i] = v[i] * inv;
}

// ============================================================
// K5: out = attn @ V per head
// ============================================================
__global__ __launch_bounds__(256) void k_av() {
    __shared__ float As[16][LDP];
    __shared__ float Bs[16][LDP];
    int bh = blockIdx.y;
    int row0 = blockIdx.x * 64;
    int tid = threadIdx.x, ty = tid >> 4, tx = tid & 15;
    const float* Abase = g_S + (size_t)bh * Nn * Nn + (size_t)row0 * Nn;
    const float* Vbase = g_V + (size_t)bh * Nn * DH;
    float acc[4][4] = {};
    for (int k0 = 0; k0 < Nn; k0 += 16) {
#pragma unroll
        for (int i = 0; i < 4; i++) {
            int f = tid + 256 * i;
            int mm = f >> 4, kk = f & 15;
            As[kk][mm] = Abase[(size_t)mm * Nn + k0 + kk];
        }
#pragma unroll
        for (int i = 0; i < 4; i++) {
            int f = tid + 256 * i;
            int kk = f >> 6, nn2 = f & 63;
            Bs[kk][nn2] = Vbase[(size_t)(k0 + kk) * DH + nn2];
        }
        __syncthreads();
#pragma unroll
        for (int kk = 0; kk < 16; kk++) {
            float4 a = *(const float4*)&As[kk][ty * 4];
            float4 b = *(const float4*)&Bs[kk][tx * 4];
            acc[0][0] += a.x * b.x; acc[0][1] += a.x * b.y; acc[0][2] += a.x * b.z; acc[0][3] += a.x * b.w;
            acc[1][0] += a.y * b.x; acc[1][1] += a.y * b.y; acc[1][2] += a.y * b.z; acc[1][3] += a.y * b.w;
            acc[2][0] += a.z * b.x; acc[2][1] += a.z * b.y; acc[2][2] += a.z * b.z; acc[2][3] += a.z * b.w;
            acc[3][0] += a.w * b.x; acc[3][1] += a.w * b.y; acc[3][2] += a.w * b.z; acc[3][3] += a.w * b.w;
        }
        __syncthreads();
    }
    int b = bh / Hh, h = bh % Hh;
#pragma unroll
    for (int i = 0; i < 4; i++) {
        int tok = row0 + ty * 4 + i;
        float4 o = make_float4(acc[i][0], acc[i][1], acc[i][2], acc[i][3]);
        *(float4*)&g_O[((size_t)(b * Nn + tok)) * INNER + h * DH + tx * 4] = o;
    }
}

// ============================================================
// K6: final projection
// ============================================================
__global__ __launch_bounds__(256) void k_proj(const float* __restrict__ wp,
                                              const float* __restrict__ bp,
                                              float* __restrict__ out) {
    __shared__ float As[16][LDP];
    __shared__ float Bs[16][LDP];
    int tid = threadIdx.x, ty = tid >> 4, tx = tid & 15;
    const float* Abase = g_O + (size_t)(blockIdx.y * 64) * INNER;
    const float* Bbase = wp + (size_t)(blockIdx.x * 64) * INNER;
    float acc[4][4] = {};
    for (int k0 = 0; k0 < INNER; k0 += 16) {
#pragma unroll
        for (int i = 0; i < 4; i++) {
            int f = tid + 256 * i;
            int mm = f >> 4, kk = f & 15;
            As[kk][mm] = Abase[(size_t)mm * INNER + k0 + kk];
            Bs[kk][mm] = Bbase[(size_t)mm * INNER + k0 + kk];
        }
        __syncthreads();
#pragma unroll
        for (int kk = 0; kk < 16; kk++) {
            float4 a = *(const float4*)&As[kk][ty * 4];
            float4 b = *(const float4*)&Bs[kk][tx * 4];
            acc[0][0] += a.x * b.x; acc[0][1] += a.x * b.y; acc[0][2] += a.x * b.z; acc[0][3] += a.x * b.w;
            acc[1][0] += a.y * b.x; acc[1][1] += a.y * b.y; acc[1][2] += a.y * b.z; acc[1][3] += a.y * b.w;
            acc[2][0] += a.z * b.x; acc[2][1] += a.z * b.y; acc[2][2] += a.z * b.z; acc[2][3] += a.z * b.w;
            acc[3][0] += a.w * b.x; acc[3][1] += a.w * b.y; acc[3][2] += a.w * b.z; acc[3][3] += a.w * b.w;
        }
        __syncthreads();
    }
    int m0 = blockIdx.y * 64 + ty * 4;
    int n0 = blockIdx.x * 64 + tx * 4;
#pragma unroll
    for (int i = 0; i < 4; i++) {
        float4 o = make_float4(acc[i][0] + bp[n0 + 0], acc[i][1] + bp[n0 + 1],
                               acc[i][2] + bp[n0 + 2], acc[i][3] + bp[n0 + 3]);
        *(float4*)&out[(size_t)(m0 + i) * Cc + n0] = o;
    }
}

extern "C" void kernel_launch(void* const* d_in, const int* in_sizes, int n_in,
                              void* d_out, int out_size) {
    const float* x      = (const float*)d_in[0];
    const float* w_qkv  = (const float*)d_in[1];
    const float* w_proj = (const float*)d_in[2];
    const float* b_proj = (const float*)d_in[3];
    const float* w_e    = (const float*)d_in[4];
    const float* b_e    = (const float*)d_in[5];
    const float* w_s    = (const float*)d_in[6];
    const float* b_s    = (const float*)d_in[7];
    const float* w_h    = (const float*)d_in[8];
    const float* b_h    = (const float*)d_in[9];
    const float* alpha  = (const float*)d_in[10];
    const float* beta   = (const float*)d_in[11];
    const float* gamma  = (const float*)d_in[12];
    const float* temp   = (const float*)d_in[13];
    float* out = (float*)d_out;

    k_qkv<<<dim3(24, 64), 256>>>(x, w_qkv);
    k_embed<<<dim3(BH * Nn / 4, 2), 256>>>(w_e, b_e, w_s, b_s, w_h, b_h);
    k_score<<<dim3(16, 16, BH), 256>>>(alpha, beta, gamma, temp);
    k_softmax<<<BH * Nn, 256>>>();
    k_av<<<dim3(16, BH), 256>>>();
    k_proj<<<dim3(8, 64), 256>>>(w_proj, b_proj, out);
}

// round 5
// speedup vs baseline: 1.8484x; 1.1346x over previous
#include <cuda_runtime.h>
#include <cuda_bf16.h>
#include <math.h>
#include <stdint.h>

#define Bsz 4
#define Nn 1024
#define Cc 512
#define Hh 8
#define DH 64
#define BH 32
#define INNER 512
#define Ff 160   // 64 (E) + 64 (S) + 32 (H)
#define LDP 68   // smem row padding

// ---- scratch (static device allocations; no runtime alloc) ----
__device__ float g_Q[BH * Nn * DH];
__device__ float g_K[BH * Nn * DH];
__device__ float g_V[BH * Nn * DH];
__device__ float g_FQ[BH * Nn * Ff];
__device__ float g_FK[BH * Nn * Ff];
__device__ float g_QA[BH * Nn];
__device__ float g_QU[BH * Nn];
__device__ float g_KB[BH * Nn];
__device__ float g_KV[BH * Nn];
__device__ float g_S[(size_t)BH * Nn * Nn];  // scores -> probs (128 MB)
__device__ float g_O[Bsz * Nn * INNER];

__device__ __forceinline__ float softplusf(float x) {
    return (x > 20.f) ? x : log1pf(expf(x));
}
__device__ __forceinline__ float fast_sqrt(float x) {
    float r; asm("sqrt.approx.f32 %0, %1;" : "=f"(r) : "f"(x)); return r;
}
__device__ __forceinline__ float fast_rcp(float x) {
    float r; asm("rcp.approx.f32 %0, %1;" : "=f"(r) : "f"(x)); return r;
}

#define MICRO_FMA(ACC, a, b)                                                                     \
    ACC[0][0] += a.x * b.x; ACC[0][1] += a.x * b.y; ACC[0][2] += a.x * b.z; ACC[0][3] += a.x * b.w; \
    ACC[1][0] += a.y * b.x; ACC[1][1] += a.y * b.y; ACC[1][2] += a.y * b.z; ACC[1][3] += a.y * b.w; \
    ACC[2][0] += a.z * b.x; ACC[2][1] += a.z * b.y; ACC[2][2] += a.z * b.z; ACC[2][3] += a.z * b.w; \
    ACC[3][0] += a.w * b.x; ACC[3][1] += a.w * b.y; ACC[3][2] += a.w * b.z; ACC[3][3] += a.w * b.w;

// ============================================================
// K1: qkv = x @ w_qkv^T, scattered into per-head Q/K/V layout
// Double-buffered, vectorized staging.
// ============================================================
__global__ __launch_bounds__(256) void k_qkv(const float* __restrict__ x,
                                             const float* __restrict__ w) {
    __shared__ float As[2][16][LDP];
    __shared__ float Bs[2][16][LDP];
    int tid = threadIdx.x;
    int ty = tid >> 4, tx = tid & 15;
    int arow = tid >> 2, aq = tid & 3;
    const float* Abase = x + (size_t)(blockIdx.y * 64) * Cc;
    const float* Bbase = w + (size_t)(blockIdx.x * 64) * Cc;
    float acc[4][4] = {};
    float4 av, bv;

    av = *(const float4*)(Abase + (size_t)arow * Cc + aq * 4);
    bv = *(const float4*)(Bbase + (size_t)arow * Cc + aq * 4);
    As[0][aq * 4 + 0][arow] = av.x; As[0][aq * 4 + 1][arow] = av.y;
    As[0][aq * 4 + 2][arow] = av.z; As[0][aq * 4 + 3][arow] = av.w;
    Bs[0][aq * 4 + 0][arow] = bv.x; Bs[0][aq * 4 + 1][arow] = bv.y;
    Bs[0][aq * 4 + 2][arow] = bv.z; Bs[0][aq * 4 + 3][arow] = bv.w;
    __syncthreads();

    for (int kt = 0; kt < 32; kt += 2) {
        if (kt + 1 < 32) {
            av = *(const float4*)(Abase + (size_t)arow * Cc + (kt + 1) * 16 + aq * 4);
            bv = *(const float4*)(Bbase + (size_t)arow * Cc + (kt + 1) * 16 + aq * 4);
        }
#pragma unroll
        for (int kk = 0; kk < 16; kk++) {
            float4 a = *(const float4*)&As[0][kk][ty * 4];
            float4 b = *(const float4*)&Bs[0][kk][tx * 4];
            MICRO_FMA(acc, a, b)
        }
        if (kt + 1 < 32) {
            As[1][aq * 4 + 0][arow] = av.x; As[1][aq * 4 + 1][arow] = av.y;
            As[1][aq * 4 + 2][arow] = av.z; As[1][aq * 4 + 3][arow] = av.w;
            Bs[1][aq * 4 + 0][arow] = bv.x; Bs[1][aq * 4 + 1][arow] = bv.y;
            Bs[1][aq * 4 + 2][arow] = bv.z; Bs[1][aq * 4 + 3][arow] = bv.w;
        }
        __syncthreads();
        if (kt + 1 < 32) {
            if (kt + 2 < 32) {
                av = *(const float4*)(Abase + (size_t)arow * Cc + (kt + 2) * 16 + aq * 4);
                bv = *(const float4*)(Bbase + (size_t)arow * Cc + (kt + 2) * 16 + aq * 4);
            }
#pragma unroll
            for (int kk = 0; kk < 16; kk++) {
                float4 a = *(const float4*)&As[1][kk][ty * 4];
                float4 b = *(const float4*)&Bs[1][kk][tx * 4];
                MICRO_FMA(acc, a, b)
            }
            if (kt + 2 < 32) {
                As[0][aq * 4 + 0][arow] = av.x; As[0][aq * 4 + 1][arow] = av.y;
                As[0][aq * 4 + 2][arow] = av.z; As[0][aq * 4 + 3][arow] = av.w;
                Bs[0][aq * 4 + 0][arow] = bv.x; Bs[0][aq * 4 + 1][arow] = bv.y;
                Bs[0][aq * 4 + 2][arow] = bv.z; Bs[0][aq * 4 + 3][arow] = bv.w;
            }
            __syncthreads();
        }
    }

    int m0 = blockIdx.y * 64 + ty * 4;
    int n0 = blockIdx.x * 64 + tx * 4;
#pragma unroll
    for (int i = 0; i < 4; i++)
#pragma unroll
        for (int j = 0; j < 4; j++) {
            int m = m0 + i, jc = n0 + j;
            int b = m / Nn, n = m % Nn;
            int part = jc / INNER, r = jc % INNER;
            int h = r / DH, d = r % DH;
            float* dst = (part == 0) ? g_Q : ((part == 1) ? g_K : g_V);
            dst[((size_t)(b * Hh + h) * Nn + n) * DH + d] = acc[i][j];
        }
}

// ============================================================
// K2: per-token metric embeddings -> packed feature rows + norm scalars
// ============================================================
__global__ __launch_bounds__(256) void k_embed(const float* __restrict__ we, const float* __restrict__ be,
                                               const float* __restrict__ ws, const float* __restrict__ bs,
                                               const float* __restrict__ wh, const float* __restrict__ bhh) {
    __shared__ float W[Ff][65];
    __shared__ float bias[Ff];
    __shared__ float qr[4][64];
    __shared__ float raw[4][Ff];
    int tid = threadIdx.x;
    for (int i = tid; i < 64 * 64; i += 256) { W[i / 64][i % 64] = we[i]; W[64 + i / 64][i % 64] = ws[i]; }
    for (int i = tid; i < 32 * 64; i += 256) W[128 + i / 64][i % 64] = wh[i];
    for (int i = tid; i < Ff; i += 256) bias[i] = (i < 64) ? be[i] : ((i < 128) ? bs[i - 64] : bhh[i - 128]);
    const float* src = (blockIdx.y == 0) ? g_Q : g_K;
    int tok0 = blockIdx.x * 4;
    for (int i = tid; i < 4 * 64; i += 256) qr[i / 64][i % 64] = src[(size_t)(tok0 + i / 64) * 64 + (i % 64)];
    __syncthreads();
    for (int i = tid; i < 4 * Ff; i += 256) {
        int tt = i / Ff, j = i % Ff;
        float s = bias[j];
#pragma unroll 8
        for (int c = 0; c < 64; c++) s += qr[tt][c] * W[j][c];
        raw[tt][j] = s;
    }
    __syncthreads();
    int w = tid >> 5, lane = tid & 31;
    if (w < 4) {
        int tt = w;
        float an = 0.f, sn = 0.f, un = 0.f;
        for (int j = lane; j < 64; j += 32) { float v = raw[tt][j]; an += v * v; }
        for (int j = 64 + lane; j < 128; j += 32) { float v = raw[tt][j]; sn += v * v; }
        {
            int j = 128 + lane;
            float th = tanhf(raw[tt][j]);
            raw[tt][j] = th;
            un += th * th;
        }
#pragma unroll
        for (int o = 16; o; o >>= 1) {
            an += __shfl_xor_sync(0xffffffffu, an, o);
            sn += __shfl_xor_sync(0xffffffffu, sn, o);
            un += __shfl_xor_sync(0xffffffffu, un, o);
        }
        float inv = 1.f / fmaxf(sqrtf(sn), 1e-12f);
        __syncwarp();
        float* Fdst = (blockIdx.y == 0) ? g_FQ : g_FK;
        int tok = tok0 + tt;
        for (int j = lane; j < Ff; j += 32) {
            float v = raw[tt][j];
            if (j >= 64 && j < 128) v *= inv;
            Fdst[(size_t)tok * Ff + j] = v;
        }
        if (lane == 0) {
            if (blockIdx.y == 0) { g_QA[tok] = an; g_QU[tok] = un; }
            else                 { g_KB[tok] = an; g_KV[tok] = un; }
        }
    }
}

// ============================================================
// K3: combined-feature GEMM (K=160, three accumulator groups)
// Double-buffered + fast distance epilogue.
// ============================================================
__global__ __launch_bounds__(256) void k_score(const float* __restrict__ alpha,
                                               const float* __restrict__ beta,
                                               const float* __restrict__ gamma,
                                               const float* __restrict__ temp) {
    __shared__ float As[2][16][LDP];
    __shared__ float Bs[2][16][LDP];
    __shared__ float sAN[64], sUN[64], sBN[64], sVN[64];
    int bh = blockIdx.z;
    int row0 = blockIdx.y * 64, col0 = blockIdx.x * 64;
    int tid = threadIdx.x, ty = tid >> 4, tx = tid & 15;
    int arow = tid >> 2, aq = tid & 3;
    const float* Abase = g_FQ + ((size_t)bh * Nn + row0) * Ff;
    const float* Bbase = g_FK + ((size_t)bh * Nn + col0) * Ff;
    if (tid < 64)       { sAN[tid] = g_QA[bh * Nn + row0 + tid]; sUN[tid] = g_QU[bh * Nn + row0 + tid]; }
    else if (tid < 128) { int t = tid - 64; sBN[t] = g_KB[bh * Nn + col0 + t]; sVN[t] = g_KV[bh * Nn + col0 + t]; }
    float accE[4][4] = {}, accS[4][4] = {}, accH[4][4] = {};
    float4 av, bv;

    av = *(const float4*)(Abase + (size_t)arow * Ff + aq * 4);
    bv = *(const float4*)(Bbase + (size_t)arow * Ff + aq * 4);
    As[0][aq * 4 + 0][arow] = av.x; As[0][aq * 4 + 1][arow] = av.y;
    As[0][aq * 4 + 2][arow] = av.z; As[0][aq * 4 + 3][arow] = av.w;
    Bs[0][aq * 4 + 0][arow] = bv.x; Bs[0][aq * 4 + 1][arow] = bv.y;
    Bs[0][aq * 4 + 2][arow] = bv.z; Bs[0][aq * 4 + 3][arow] = bv.w;
    __syncthreads();

#define SC_LDG(KT) \
    av = *(const float4*)(Abase + (size_t)arow * Ff + (KT) * 16 + aq * 4); \
    bv = *(const float4*)(Bbase + (size_t)arow * Ff + (KT) * 16 + aq * 4);
#define SC_STS(BUF) \
    As[BUF][aq * 4 + 0][arow] = av.x; As[BUF][aq * 4 + 1][arow] = av.y; \
    As[BUF][aq * 4 + 2][arow] = av.z; As[BUF][aq * 4 + 3][arow] = av.w; \
    Bs[BUF][aq * 4 + 0][arow] = bv.x; Bs[BUF][aq * 4 + 1][arow] = bv.y; \
    Bs[BUF][aq * 4 + 2][arow] = bv.z; Bs[BUF][aq * 4 + 3][arow] = bv.w;
#define SC_COMP(BUF, ACC) \
    _Pragma("unroll") \
    for (int kk = 0; kk < 16; kk++) { \
        float4 a = *(const float4*)&As[BUF][kk][ty * 4]; \
        float4 b = *(const float4*)&Bs[BUF][kk][tx * 4]; \
        MICRO_FMA(ACC, a, b) \
    }
#define SC_PAIR(KT, ACC, LAST) \
    SC_LDG(KT + 1) \
    SC_COMP(0, ACC) \
    SC_STS(1) \
    __syncthreads(); \
    if (!(LAST)) { SC_LDG(KT + 2) } \
    SC_COMP(1, ACC) \
    if (!(LAST)) { SC_STS(0) } \
    __syncthreads();

    SC_PAIR(0, accE, false)
    SC_PAIR(2, accE, false)
    SC_PAIR(4, accS, false)
    SC_PAIR(6, accS, false)
    // last pair: kt 8,9 (group H)
    SC_LDG(9)
    SC_COMP(0, accH)
    SC_STS(1)
    __syncthreads();
    SC_COMP(1, accH)

    float cE = softplusf(alpha[0]);
    float cS = softplusf(beta[0]);
    float cH = softplusf(gamma[0]);
    float negInvT = -1.f / softplusf(temp[0]);
    float* Sbase = g_S + (size_t)bh * Nn * Nn;
#pragma unroll
    for (int i = 0; i < 4; i++) {
        int r = row0 + ty * 4 + i;
        float an = sAN[ty * 4 + i], un = sUN[ty * 4 + i];
        float one_m_un = 1.f - un;
        float4 o;
        float* op = (float*)&o;
#pragma unroll
        for (int j = 0; j < 4; j++) {
            int cidx = tx * 4 + j;
            float bn = sBN[cidx], vn = sVN[cidx];
            float dE = fast_sqrt(fmaxf(an + bn - 2.f * accE[i][j], 1e-12f));
            float x = fminf(fmaxf(accS[i][j], -1.f + 1e-6f), 1.f - 1e-6f);
            float ax = fabsf(x);
            float poly = fmaf(ax, fmaf(ax, fmaf(ax, -0.0187293f, 0.0742610f), -0.2121144f), 1.5707288f);
            float rr = fast_sqrt(1.f - ax) * poly;
            float dS = (x >= 0.f) ? rr : (3.14159265358979f - rr);
            float dns = fmaxf(un + vn - 2.f * accH[i][j], 0.f);
            float denom = one_m_un * (1.f - vn) + 1e-8f;
            float t = fmaxf(2.f * dns * fast_rcp(denom), 1e-6f);
            float sh = fast_sqrt(t * (t + 2.f));
            float dHp = __logf(1.f + t + sh);
            op[j] = negInvT * (cE * dE + cS * dS + cH * dHp);
        }
        *(float4*)&Sbase[(size_t)r * Nn + col0 + tx * 4] = o;
    }
}

// ============================================================
// K4: row softmax in place over g_S
// ============================================================
__global__ __launch_bounds__(256) void k_softmax() {
    __shared__ float red[8];
    size_t base = (size_t)blockIdx.x * Nn;
    int tid = threadIdx.x;
    float v[4];
#pragma unroll
    for (int i = 0; i < 4; i++) v[i] = g_S[base + tid + 256 * i];
    float m = fmaxf(fmaxf(v[0], v[1]), fmaxf(v[2], v[3]));
#pragma unroll
    for (int o = 16; o; o >>= 1) m = fmaxf(m, __shfl_xor_sync(0xffffffffu, m, o));
    if ((tid & 31) == 0) red[tid >> 5] = m;
    __syncthreads();
    float M = red[0];
#pragma unroll
    for (int i = 1; i < 8; i++) M = fmaxf(M, red[i]);
    float s = 0.f;
#pragma unroll
    for (int i = 0; i < 4; i++) { v[i] = __expf(v[i] - M); s += v[i]; }
#pragma unroll
    for (int o = 16; o; o >>= 1) s += __shfl_xor_sync(0xffffffffu, s, o);
    __syncthreads();
    if ((tid & 31) == 0) red[tid >> 5] = s;
    __syncthreads();
    float S = 0.f;
#pragma unroll
    for (int i = 0; i < 8; i++) S += red[i];
    float inv = 1.f / S;
#pragma unroll
    for (int i = 0; i < 4; i++) g_S[base + tid + 256 * i] = v[i] * inv;
}

// ============================================================
// K5: out = attn @ V per head (double-buffered)
// ============================================================
__global__ __launch_bounds__(256) void k_av() {
    __shared__ float As[2][16][LDP];
    __shared__ float Bs[2][16][LDP];
    int bh = blockIdx.y;
    int row0 = blockIdx.x * 64;
    int tid = threadIdx.x, ty = tid >> 4, tx = tid & 15;
    int arow = tid >> 2, aq = tid & 3;      // A staging: 64 rows x 1 float4
    int brow = tid >> 4, bq = tid & 15;     // B staging: 16 rows x 16 float4
    const float* Abase = g_S + (size_t)bh * Nn * Nn + (size_t)row0 * Nn;
    const float* Vbase = g_V + (size_t)bh * Nn * DH;
    float acc[4][4] = {};
    float4 av, bv;

    av = *(const float4*)(Abase + (size_t)arow * Nn + aq * 4);
    bv = *(const float4*)(Vbase + (size_t)brow * DH + bq * 4);
    As[0][aq * 4 + 0][arow] = av.x; As[0][aq * 4 + 1][arow] = av.y;
    As[0][aq * 4 + 2][arow] = av.z; As[0][aq * 4 + 3][arow] = av.w;
    *(float4*)&Bs[0][brow][bq * 4] = bv;
    __syncthreads();

    for (int kt = 0; kt < 64; kt += 2) {
        if (kt + 1 < 64) {
            av = *(const float4*)(Abase + (size_t)arow * Nn + (kt + 1) * 16 + aq * 4);
            bv = *(const float4*)(Vbase + (size_t)((kt + 1) * 16 + brow) * DH + bq * 4);
        }
#pragma unroll
        for (int kk = 0; kk < 16; kk++) {
            float4 a = *(const float4*)&As[0][kk][ty * 4];
            float4 b = *(const float4*)&Bs[0][kk][tx * 4];
            MICRO_FMA(acc, a, b)
        }
        if (kt + 1 < 64) {
            As[1][aq * 4 + 0][arow] = av.x; As[1][aq * 4 + 1][arow] = av.y;
            As[1][aq * 4 + 2][arow] = av.z; As[1][aq * 4 + 3][arow] = av.w;
            *(float4*)&Bs[1][brow][bq * 4] = bv;
        }
        __syncthreads();
        if (kt + 1 < 64) {
            if (kt + 2 < 64) {
                av = *(const float4*)(Abase + (size_t)arow * Nn + (kt + 2) * 16 + aq * 4);
                bv = *(const float4*)(Vbase + (size_t)((kt + 2) * 16 + brow) * DH + bq * 4);
            }
#pragma unroll
            for (int kk = 0; kk < 16; kk++) {
                float4 a = *(const float4*)&As[1][kk][ty * 4];
                float4 b = *(const float4*)&Bs[1][kk][tx * 4];
                MICRO_FMA(acc, a, b)
            }
            if (kt + 2 < 64) {
                As[0][aq * 4 + 0][arow] = av.x; As[0][aq * 4 + 1][arow] = av.y;
                As[0][aq * 4 + 2][arow] = av.z; As[0][aq * 4 + 3][arow] = av.w;
                *(float4*)&Bs[0][brow][bq * 4] = bv;
            }
            __syncthreads();
        }
    }

    int b = bh / Hh, h = bh % Hh;
#pragma unroll
    for (int i = 0; i < 4; i++) {
        int tok = row0 + ty * 4 + i;
        float4 o = make_float4(acc[i][0], acc[i][1], acc[i][2], acc[i][3]);
        *(float4*)&g_O[((size_t)(b * Nn + tok)) * INNER + h * DH + tx * 4] = o;
    }
}

// ============================================================
// K6: final projection (double-buffered)
// ============================================================
__global__ __launch_bounds__(256) void k_proj(const float* __restrict__ wp,
                                              const float* __restrict__ bp,
                                              float* __restrict__ out) {
    __shared__ float As[2][16][LDP];
    __shared__ float Bs[2][16][LDP];
    int tid = threadIdx.x, ty = tid >> 4, tx = tid & 15;
    int arow = tid >> 2, aq = tid & 3;
    const float* Abase = g_O + (size_t)(blockIdx.y * 64) * INNER;
    const float* Bbase = wp + (size_t)(blockIdx.x * 64) * INNER;
    float acc[4][4] = {};
    float4 av, bv;

    av = *(const float4*)(Abase + (size_t)arow * INNER + aq * 4);
    bv = *(const float4*)(Bbase + (size_t)arow * INNER + aq * 4);
    As[0][aq * 4 + 0][arow] = av.x; As[0][aq * 4 + 1][arow] = av.y;
    As[0][aq * 4 + 2][arow] = av.z; As[0][aq * 4 + 3][arow] = av.w;
    Bs[0][aq * 4 + 0][arow] = bv.x; Bs[0][aq * 4 + 1][arow] = bv.y;
    Bs[0][aq * 4 + 2][arow] = bv.z; Bs[0][aq * 4 + 3][arow] = bv.w;
    __syncthreads();

    for (int kt = 0; kt < 32; kt += 2) {
        if (kt + 1 < 32) {
            av = *(const float4*)(Abase + (size_t)arow * INNER + (kt + 1) * 16 + aq * 4);
            bv = *(const float4*)(Bbase + (size_t)arow * INNER + (kt + 1) * 16 + aq * 4);
        }
#pragma unroll
        for (int kk = 0; kk < 16; kk++) {
            float4 a = *(const float4*)&As[0][kk][ty * 4];
            float4 b = *(const float4*)&Bs[0][kk][tx * 4];
            MICRO_FMA(acc, a, b)
        }
        if (kt + 1 < 32) {
            As[1][aq * 4 + 0][arow] = av.x; As[1][aq * 4 + 1][arow] = av.y;
            As[1][aq * 4 + 2][arow] = av.z; As[1][aq * 4 + 3][arow] = av.w;
            Bs[1][aq * 4 + 0][arow] = bv.x; Bs[1][aq * 4 + 1][arow] = bv.y;
            Bs[1][aq * 4 + 2][arow] = bv.z; Bs[1][aq * 4 + 3][arow] = bv.w;
        }
        __syncthreads();
        if (kt + 1 < 32) {
            if (kt + 2 < 32) {
                av = *(const float4*)(Abase + (size_t)arow * INNER + (kt + 2) * 16 + aq * 4);
                bv = *(const float4*)(Bbase + (size_t)arow * INNER + (kt + 2) * 16 + aq * 4);
            }
#pragma unroll
            for (int kk = 0; kk < 16; kk++) {
                float4 a = *(const float4*)&As[1][kk][ty * 4];
                float4 b = *(const float4*)&Bs[1][kk][tx * 4];
                MICRO_FMA(acc, a, b)
            }
            if (kt + 2 < 32) {
                As[0][aq * 4 + 0][arow] = av.x; As[0][aq * 4 + 1][arow] = av.y;
                As[0][aq * 4 + 2][arow] = av.z; As[0][aq * 4 + 3][arow] = av.w;
                Bs[0][aq * 4 + 0][arow] = bv.x; Bs[0][aq * 4 + 1][arow] = bv.y;
                Bs[0][aq * 4 + 2][arow] = bv.z; Bs[0][aq * 4 + 3][arow] = bv.w;
            }
            __syncthreads();
        }
    }

    int m0 = blockIdx.y * 64 + ty * 4;
    int n0 = blockIdx.x * 64 + tx * 4;
#pragma unroll
    for (int i = 0; i < 4; i++) {
        float4 o = make_float4(acc[i][0] + bp[n0 + 0], acc[i][1] + bp[n0 + 1],
                               acc[i][2] + bp[n0 + 2], acc[i][3] + bp[n0 + 3]);
        *(float4*)&out[(size_t)(m0 + i) * Cc + n0] = o;
    }
}

extern "C" void kernel_launch(void* const* d_in, const int* in_sizes, int n_in,
                              void* d_out, int out_size) {
    const float* x      = (const float*)d_in[0];
    const float* w_qkv  = (const float*)d_in[1];
    const float* w_proj = (const float*)d_in[2];
    const float* b_proj = (const float*)d_in[3];
    const float* w_e    = (const float*)d_in[4];
    const float* b_e    = (const float*)d_in[5];
    const float* w_s    = (const float*)d_in[6];
    const float* b_s    = (const float*)d_in[7];
    const float* w_h    = (const float*)d_in[8];
    const float* b_h    = (const float*)d_in[9];
    const float* alpha  = (const float*)d_in[10];
    const float* beta   = (const float*)d_in[11];
    const float* gamma  = (const float*)d_in[12];
    const float* temp   = (const float*)d_in[13];
    float* out = (float*)d_out;

    k_qkv<<<dim3(24, 64), 256>>>(x, w_qkv);
    k_embed<<<dim3(BH * Nn / 4, 2), 256>>>(w_e, b_e, w_s, b_s, w_h, b_h);
    k_score<<<dim3(16, 16, BH), 256>>>(alpha, beta, gamma, temp);
    k_softmax<<<BH * Nn, 256>>>();
    k_av<<<dim3(16, BH), 256>>>();
    k_proj<<<dim3(8, 64), 256>>>(w_proj, b_proj, out);
}

// round 7
// speedup vs baseline: 1.8564x; 1.0043x over previous
#include <cuda_runtime.h>
#include <cuda_bf16.h>
#include <math.h>
#include <stdint.h>

#define Bsz 4
#define Nn 1024
#define Cc 512
#define Hh 8
#define DH 64
#define BH 32
#define INNER 512
#define Ff 160   // 64 (E) + 64 (S) + 32 (H)
#define LDP 68   // smem row padding

typedef unsigned long long u64;

// ---- scratch (static device allocations; no runtime alloc) ----
__device__ float g_Q[BH * Nn * DH];
__device__ float g_K[BH * Nn * DH];
__device__ float g_V[BH * Nn * DH];
__device__ float g_FQ[BH * Nn * Ff];
__device__ float g_FK[BH * Nn * Ff];
__device__ float g_QA[BH * Nn];
__device__ float g_QU[BH * Nn];
__device__ float g_KB[BH * Nn];
__device__ float g_KV[BH * Nn];
__device__ float g_S[(size_t)BH * Nn * Nn];  // scores -> probs (128 MB)
__device__ float g_O[Bsz * Nn * INNER];

__device__ __forceinline__ float softplusf(float x) {
    return (x > 20.f) ? x : log1pf(expf(x));
}
__device__ __forceinline__ float fast_sqrt(float x) {
    float r; asm("sqrt.approx.f32 %0, %1;" : "=f"(r) : "f"(x)); return r;
}
__device__ __forceinline__ float fast_rcp(float x) {
    float r; asm("rcp.approx.f32 %0, %1;" : "=f"(r) : "f"(x)); return r;
}

// ---- packed f32x2 FMA (Blackwell FFMA2 path) ----
__device__ __forceinline__ void fma2(u64& d, u64 a, u64 b) {
    asm("fma.rn.f32x2 %0, %1, %2, %0;" : "+l"(d) : "l"(a), "l"(b));
}
__device__ __forceinline__ u64 pack2(float lo, float hi) {
    u64 r; asm("mov.b64 %0, {%1, %2};" : "=l"(r) : "f"(lo), "f"(hi)); return r;
}
__device__ __forceinline__ void unpack2(u64 v, float& lo, float& hi) {
    asm("mov.b64 {%0, %1}, %2;" : "=f"(lo), "=f"(hi) : "l"(v));
}

// 4x4 microtile as 4 rows x 2 packed column-pairs, 8 FFMA2 per kk
#define MICRO_FMA2(ACC2, a, b)                                   \
    {                                                            \
        u64 b01 = pack2(b.x, b.y), b23 = pack2(b.z, b.w);        \
        u64 ar;                                                  \
        ar = pack2(a.x, a.x); fma2(ACC2[0][0], ar, b01); fma2(ACC2[0][1], ar, b23); \
        ar = pack2(a.y, a.y); fma2(ACC2[1][0], ar, b01); fma2(ACC2[1][1], ar, b23); \
        ar = pack2(a.z, a.z); fma2(ACC2[2][0], ar, b01); fma2(ACC2[2][1], ar, b23); \
        ar = pack2(a.w, a.w); fma2(ACC2[3][0], ar, b01); fma2(ACC2[3][1], ar, b23); \
    }

#define UNPACK_ACC(ACC2, ACC)                                    \
    _Pragma("unroll")                                            \
    for (int _i = 0; _i < 4; _i++) {                             \
        unpack2(ACC2[_i][0], ACC[_i][0], ACC[_i][1]);            \
        unpack2(ACC2[_i][1], ACC[_i][2], ACC[_i][3]);            \
    }

// ============================================================
// K1: qkv = x @ w_qkv^T, scattered into per-head Q/K/V layout
// ============================================================
__global__ __launch_bounds__(256) void k_qkv(const float* __restrict__ x,
                                             const float* __restrict__ w) {
    __shared__ float As[2][16][LDP];
    __shared__ float Bs[2][16][LDP];
    int tid = threadIdx.x;
    int ty = tid >> 4, tx = tid & 15;
    int arow = tid >> 2, aq = tid & 3;
    const float* Abase = x + (size_t)(blockIdx.y * 64) * Cc;
    const float* Bbase = w + (size_t)(blockIdx.x * 64) * Cc;
    u64 acc2[4][2] = {};
    float4 av, bv;

    av = *(const float4*)(Abase + (size_t)arow * Cc + aq * 4);
    bv = *(const float4*)(Bbase + (size_t)arow * Cc + aq * 4);
    As[0][aq * 4 + 0][arow] = av.x; As[0][aq * 4 + 1][arow] = av.y;
    As[0][aq * 4 + 2][arow] = av.z; As[0][aq * 4 + 3][arow] = av.w;
    Bs[0][aq * 4 + 0][arow] = bv.x; Bs[0][aq * 4 + 1][arow] = bv.y;
    Bs[0][aq * 4 + 2][arow] = bv.z; Bs[0][aq * 4 + 3][arow] = bv.w;
    __syncthreads();

    for (int kt = 0; kt < 32; kt += 2) {
        if (kt + 1 < 32) {
            av = *(const float4*)(Abase + (size_t)arow * Cc + (kt + 1) * 16 + aq * 4);
            bv = *(const float4*)(Bbase + (size_t)arow * Cc + (kt + 1) * 16 + aq * 4);
        }
#pragma unroll
        for (int kk = 0; kk < 16; kk++) {
            float4 a = *(const float4*)&As[0][kk][ty * 4];
            float4 b = *(const float4*)&Bs[0][kk][tx * 4];
            MICRO_FMA2(acc2, a, b)
        }
        if (kt + 1 < 32) {
            As[1][aq * 4 + 0][arow] = av.x; As[1][aq * 4 + 1][arow] = av.y;
            As[1][aq * 4 + 2][arow] = av.z; As[1][aq * 4 + 3][arow] = av.w;
            Bs[1][aq * 4 + 0][arow] = bv.x; Bs[1][aq * 4 + 1][arow] = bv.y;
            Bs[1][aq * 4 + 2][arow] = bv.z; Bs[1][aq * 4 + 3][arow] = bv.w;
        }
        __syncthreads();
        if (kt + 1 < 32) {
            if (kt + 2 < 32) {
                av = *(const float4*)(Abase + (size_t)arow * Cc + (kt + 2) * 16 + aq * 4);
                bv = *(const float4*)(Bbase + (size_t)arow * Cc + (kt + 2) * 16 + aq * 4);
            }
#pragma unroll
            for (int kk = 0; kk < 16; kk++) {
                float4 a = *(const float4*)&As[1][kk][ty * 4];
                float4 b = *(const float4*)&Bs[1][kk][tx * 4];
                MICRO_FMA2(acc2, a, b)
            }
            if (kt + 2 < 32) {
                As[0][aq * 4 + 0][arow] = av.x; As[0][aq * 4 + 1][arow] = av.y;
                As[0][aq * 4 + 2][arow] = av.z; As[0][aq * 4 + 3][arow] = av.w;
                Bs[0][aq * 4 + 0][arow] = bv.x; Bs[0][aq * 4 + 1][arow] = bv.y;
                Bs[0][aq * 4 + 2][arow] = bv.z; Bs[0][aq * 4 + 3][arow] = bv.w;
            }
            __syncthreads();
        }
    }

    float acc[4][4];
    UNPACK_ACC(acc2, acc)
    int m0 = blockIdx.y * 64 + ty * 4;
    int n0 = blockIdx.x * 64 + tx * 4;
#pragma unroll
    for (int i = 0; i < 4; i++)
#pragma unroll
        for (int j = 0; j < 4; j++) {
            int m = m0 + i, jc = n0 + j;
            int b = m / Nn, n = m % Nn;
            int part = jc / INNER, r = jc % INNER;
            int h = r / DH, d = r % DH;
            float* dst = (part == 0) ? g_Q : ((part == 1) ? g_K : g_V);
            dst[((size_t)(b * Hh + h) * Nn + n) * DH + d] = acc[i][j];
        }
}

// ============================================================
// K2: per-token metric embeddings -> packed feature rows + norm scalars
// ============================================================
__global__ __launch_bounds__(256) void k_embed(const float* __restrict__ we, const float* __restrict__ be,
                                               const float* __restrict__ ws, const float* __restrict__ bs,
                                               const float* __restrict__ wh, const float* __restrict__ bhh) {
    __shared__ float W[Ff][65];
    __shared__ float bias[Ff];
    __shared__ float qr[4][64];
    __shared__ float raw[4][Ff];
    int tid = threadIdx.x;
    for (int i = tid; i < 64 * 64; i += 256) { W[i / 64][i % 64] = we[i]; W[64 + i / 64][i % 64] = ws[i]; }
    for (int i = tid; i < 32 * 64; i += 256) W[128 + i / 64][i % 64] = wh[i];
    for (int i = tid; i < Ff; i += 256) bias[i] = (i < 64) ? be[i] : ((i < 128) ? bs[i - 64] : bhh[i - 128]);
    const float* src = (blockIdx.y == 0) ? g_Q : g_K;
    int tok0 = blockIdx.x * 4;
    for (int i = tid; i < 4 * 64; i += 256) qr[i / 64][i % 64] = src[(size_t)(tok0 + i / 64) * 64 + (i % 64)];
    __syncthreads();
    for (int i = tid; i < 4 * Ff; i += 256) {
        int tt = i / Ff, j = i % Ff;
        float s = bias[j];
#pragma unroll 8
        for (int c = 0; c < 64; c++) s += qr[tt][c] * W[j][c];
        raw[tt][j] = s;
    }
    __syncthreads();
    int w = tid >> 5, lane = tid & 31;
    if (w < 4) {
        int tt = w;
        float an = 0.f, sn = 0.f, un = 0.f;
        for (int j = lane; j < 64; j += 32) { float v = raw[tt][j]; an += v * v; }
        for (int j = 64 + lane; j < 128; j += 32) { float v = raw[tt][j]; sn += v * v; }
        {
            int j = 128 + lane;
            float th = tanhf(raw[tt][j]);
            raw[tt][j] = th;
            un += th * th;
        }
#pragma unroll
        for (int o = 16; o; o >>= 1) {
            an += __shfl_xor_sync(0xffffffffu, an, o);
            sn += __shfl_xor_sync(0xffffffffu, sn, o);
            un += __shfl_xor_sync(0xffffffffu, un, o);
        }
        float inv = 1.f / fmaxf(sqrtf(sn), 1e-12f);
        __syncwarp();
        float* Fdst = (blockIdx.y == 0) ? g_FQ : g_FK;
        int tok = tok0 + tt;
        for (int j = lane; j < Ff; j += 32) {
            float v = raw[tt][j];
            if (j >= 64 && j < 128) v *= inv;
            Fdst[(size_t)tok * Ff + j] = v;
        }
        if (lane == 0) {
            if (blockIdx.y == 0) { g_QA[tok] = an; g_QU[tok] = un; }
            else                 { g_KB[tok] = an; g_KV[tok] = un; }
        }
    }
}

// ============================================================
// K3: combined-feature GEMM (K=160, three accumulator groups)
// Double-buffered + FFMA2 + fast distance epilogue.
// ============================================================
__global__ __launch_bounds__(256) void k_score(const float* __restrict__ alpha,
                                               const float* __restrict__ beta,
                                               const float* __restrict__ gamma,
                                               const float* __restrict__ temp) {
    __shared__ float As[2][16][LDP];
    __shared__ float Bs[2][16][LDP];
    __shared__ float sAN[64], sUN[64], sBN[64], sVN[64];
    int bh = blockIdx.z;
    int row0 = blockIdx.y * 64, col0 = blockIdx.x * 64;
    int tid = threadIdx.x, ty = tid >> 4, tx = tid & 15;
    int arow = tid >> 2, aq = tid & 3;
    const float* Abase = g_FQ + ((size_t)bh * Nn + row0) * Ff;
    const float* Bbase = g_FK + ((size_t)bh * Nn + col0) * Ff;
    if (tid < 64)       { sAN[tid] = g_QA[bh * Nn + row0 + tid]; sUN[tid] = g_QU[bh * Nn + row0 + tid]; }
    else if (tid < 128) { int t = tid - 64; sBN[t] = g_KB[bh * Nn + col0 + t]; sVN[t] = g_KV[bh * Nn + col0 + t]; }
    u64 accE2[4][2] = {}, accS2[4][2] = {}, accH2[4][2] = {};
    float4 av, bv;

    av = *(const float4*)(Abase + (size_t)arow * Ff + aq * 4);
    bv = *(const float4*)(Bbase + (size_t)arow * Ff + aq * 4);
    As[0][aq * 4 + 0][arow] = av.x; As[0][aq * 4 + 1][arow] = av.y;
    As[0][aq * 4 + 2][arow] = av.z; As[0][aq * 4 + 3][arow] = av.w;
    Bs[0][aq * 4 + 0][arow] = bv.x; Bs[0][aq * 4 + 1][arow] = bv.y;
    Bs[0][aq * 4 + 2][arow] = bv.z; Bs[0][aq * 4 + 3][arow] = bv.w;
    __syncthreads();

#define SC_LDG(KT) \
    av = *(const float4*)(Abase + (size_t)arow * Ff + (KT) * 16 + aq * 4); \
    bv = *(const float4*)(Bbase + (size_t)arow * Ff + (KT) * 16 + aq * 4);
#define SC_STS(BUF) \
    As[BUF][aq * 4 + 0][arow] = av.x; As[BUF][aq * 4 + 1][arow] = av.y; \
    As[BUF][aq * 4 + 2][arow] = av.z; As[BUF][aq * 4 + 3][arow] = av.w; \
    Bs[BUF][aq * 4 + 0][arow] = bv.x; Bs[BUF][aq * 4 + 1][arow] = bv.y; \
    Bs[BUF][aq * 4 + 2][arow] = bv.z; Bs[BUF][aq * 4 + 3][arow] = bv.w;
#define SC_COMP(BUF, ACC2) \
    _Pragma("unroll") \
    for (int kk = 0; kk < 16; kk++) { \
        float4 a = *(const float4*)&As[BUF][kk][ty * 4]; \
        float4 b = *(const float4*)&Bs[BUF][kk][tx * 4]; \
        MICRO_FMA2(ACC2, a, b) \
    }
#define SC_PAIR(KT, ACC2, LAST) \
    SC_LDG(KT + 1) \
    SC_COMP(0, ACC2) \
    SC_STS(1) \
    __syncthreads(); \
    if (!(LAST)) { SC_LDG(KT + 2) } \
    SC_COMP(1, ACC2) \
    if (!(LAST)) { SC_STS(0) } \
    __syncthreads();

    SC_PAIR(0, accE2, false)
    SC_PAIR(2, accE2, false)
    SC_PAIR(4, accS2, false)
    SC_PAIR(6, accS2, false)
    // last pair: kt 8,9 (group H)
    SC_LDG(9)
    SC_COMP(0, accH2)
    SC_STS(1)
    __syncthreads();
    SC_COMP(1, accH2)

    float accE[4][4], accS[4][4], accH[4][4];
    UNPACK_ACC(accE2, accE)
    UNPACK_ACC(accS2, accS)
    UNPACK_ACC(accH2, accH)

    float cE = softplusf(alpha[0]);
    float cS = softplusf(beta[0]);
    float cH = softplusf(gamma[0]);
    float negInvT = -1.f / softplusf(temp[0]);
    float* Sbase = g_S + (size_t)bh * Nn * Nn;
#pragma unroll
    for (int i = 0; i < 4; i++) {
        int r = row0 + ty * 4 + i;
        float an = sAN[ty * 4 + i], un = sUN[ty * 4 + i];
        float one_m_un = 1.f - un;
        float4 o;
        float* op = (float*)&o;
#pragma unroll
        for (int j = 0; j < 4; j++) {
            int cidx = tx * 4 + j;
            float bn = sBN[cidx], vn = sVN[cidx];
            float dE = fast_sqrt(fmaxf(an + bn - 2.f * accE[i][j], 1e-12f));
            float x = fminf(fmaxf(accS[i][j], -1.f + 1e-6f), 1.f - 1e-6f);
            float ax = fabsf(x);
            float poly = fmaf(ax, fmaf(ax, fmaf(ax, -0.0187293f, 0.0742610f), -0.2121144f), 1.5707288f);
            float rr = fast_sqrt(1.f - ax) * poly;
            float dS = (x >= 0.f) ? rr : (3.14159265358979f - rr);
            float dns = fmaxf(un + vn - 2.f * accH[i][j], 0.f);
            float denom = one_m_un * (1.f - vn) + 1e-8f;
            float t = fmaxf(2.f * dns * fast_rcp(denom), 1e-6f);
            float sh = fast_sqrt(t * (t + 2.f));
            float dHp = __logf(1.f + t + sh);
            op[j] = negInvT * (cE * dE + cS * dS + cH * dHp);
        }
        *(float4*)&Sbase[(size_t)r * Nn + col0 + tx * 4] = o;
    }
}

// ============================================================
// K4: row softmax in place over g_S
// ============================================================
__global__ __launch_bounds__(256) void k_softmax() {
    __shared__ float red[8];
    size_t base = (size_t)blockIdx.x * Nn;
    int tid = threadIdx.x;
    float v[4];
#pragma unroll
    for (int i = 0; i < 4; i++) v[i] = g_S[base + tid + 256 * i];
    float m = fmaxf(fmaxf(v[0], v[1]), fmaxf(v[2], v[3]));
#pragma unroll
    for (int o = 16; o; o >>= 1) m = fmaxf(m, __shfl_xor_sync(0xffffffffu, m, o));
    if ((tid & 31) == 0) red[tid >> 5] = m;
    __syncthreads();
    float M = red[0];
#pragma unroll
    for (int i = 1; i < 8; i++) M = fmaxf(M, red[i]);
    float s = 0.f;
#pragma unroll
    for (int i = 0; i < 4; i++) { v[i] = __expf(v[i] - M); s += v[i]; }
#pragma unroll
    for (int o = 16; o; o >>= 1) s += __shfl_xor_sync(0xffffffffu, s, o);
    __syncthreads();
    if ((tid & 31) == 0) red[tid >> 5] = s;
    __syncthreads();
    float S = 0.f;
#pragma unroll
    for (int i = 0; i < 8; i++) S += red[i];
    float inv = 1.f / S;
#pragma unroll
    for (int i = 0; i < 4; i++) g_S[base + tid + 256 * i] = v[i] * inv;
}

// ============================================================
// K5: out = attn @ V per head (double-buffered, FFMA2)
// ============================================================
__global__ __launch_bounds__(256) void k_av() {
    __shared__ float As[2][16][LDP];
    __shared__ float Bs[2][16][LDP];
    int bh = blockIdx.y;
    int row0 = blockIdx.x * 64;
    int tid = threadIdx.x, ty = tid >> 4, tx = tid & 15;
    int arow = tid >> 2, aq = tid & 3;
    int brow = tid >> 4, bq = tid & 15;
    const float* Abase = g_S + (size_t)bh * Nn * Nn + (size_t)row0 * Nn;
    const float* Vbase = g_V + (size_t)bh * Nn * DH;
    u64 acc2[4][2] = {};
    float4 av, bv;

    av = *(const float4*)(Abase + (size_t)arow * Nn + aq * 4);
    bv = *(const float4*)(Vbase + (size_t)brow * DH + bq * 4);
    As[0][aq * 4 + 0][arow] = av.x; As[0][aq * 4 + 1][arow] = av.y;
    As[0][aq * 4 + 2][arow] = av.z; As[0][aq * 4 + 3][arow] = av.w;
    *(float4*)&Bs[0][brow][bq * 4] = bv;
    __syncthreads();

    for (int kt = 0; kt < 64; kt += 2) {
        if (kt + 1 < 64) {
            av = *(const float4*)(Abase + (size_t)arow * Nn + (kt + 1) * 16 + aq * 4);
            bv = *(const float4*)(Vbase + (size_t)((kt + 1) * 16 + brow) * DH + bq * 4);
        }
#pragma unroll
        for (int kk = 0; kk < 16; kk++) {
            float4 a = *(const float4*)&As[0][kk][ty * 4];
            float4 b = *(const float4*)&Bs[0][kk][tx * 4];
            MICRO_FMA2(acc2, a, b)
        }
        if (kt + 1 < 64) {
            As[1][aq * 4 + 0][arow] = av.x; As[1][aq * 4 + 1][arow] = av.y;
            As[1][aq * 4 + 2][arow] = av.z; As[1][aq * 4 + 3][arow] = av.w;
            *(float4*)&Bs[1][brow][bq * 4] = bv;
        }
        __syncthreads();
        if (kt + 1 < 64) {
            if (kt + 2 < 64) {
                av = *(const float4*)(Abase + (size_t)arow * Nn + (kt + 2) * 16 + aq * 4);
                bv = *(const float4*)(Vbase + (size_t)((kt + 2) * 16 + brow) * DH + bq * 4);
            }
#pragma unroll
            for (int kk = 0; kk < 16; kk++) {
                float4 a = *(const float4*)&As[1][kk][ty * 4];
                float4 b = *(const float4*)&Bs[1][kk][tx * 4];
                MICRO_FMA2(acc2, a, b)
            }
            if (kt + 2 < 64) {
                As[0][aq * 4 + 0][arow] = av.x; As[0][aq * 4 + 1][arow] = av.y;
                As[0][aq * 4 + 2][arow] = av.z; As[0][aq * 4 + 3][arow] = av.w;
                *(float4*)&Bs[0][brow][bq * 4] = bv;
            }
            __syncthreads();
        }
    }

    float acc[4][4];
    UNPACK_ACC(acc2, acc)
    int b = bh / Hh, h = bh % Hh;
#pragma unroll
    for (int i = 0; i < 4; i++) {
        int tok = row0 + ty * 4 + i;
        float4 o = make_float4(acc[i][0], acc[i][1], acc[i][2], acc[i][3]);
        *(float4*)&g_O[((size_t)(b * Nn + tok)) * INNER + h * DH + tx * 4] = o;
    }
}

// ============================================================
// K6: final projection (double-buffered, FFMA2)
// ============================================================
__global__ __launch_bounds__(256) void k_proj(const float* __restrict__ wp,
                                              const float* __restrict__ bp,
                                              float* __restrict__ out) {
    __shared__ float As[2][16][LDP];
    __shared__ float Bs[2][16][LDP];
    int tid = threadIdx.x, ty = tid >> 4, tx = tid & 15;
    int arow = tid >> 2, aq = tid & 3;
    const float* Abase = g_O + (size_t)(blockIdx.y * 64) * INNER;
    const float* Bbase = wp + (size_t)(blockIdx.x * 64) * INNER;
    u64 acc2[4][2] = {};
    float4 av, bv;

    av = *(const float4*)(Abase + (size_t)arow * INNER + aq * 4);
    bv = *(const float4*)(Bbase + (size_t)arow * INNER + aq * 4);
    As[0][aq * 4 + 0][arow] = av.x; As[0][aq * 4 + 1][arow] = av.y;
    As[0][aq * 4 + 2][arow] = av.z; As[0][aq * 4 + 3][arow] = av.w;
    Bs[0][aq * 4 + 0][arow] = bv.x; Bs[0][aq * 4 + 1][arow] = bv.y;
    Bs[0][aq * 4 + 2][arow] = bv.z; Bs[0][aq * 4 + 3][arow] = bv.w;
    __syncthreads();

    for (int kt = 0; kt < 32; kt += 2) {
        if (kt + 1 < 32) {
            av = *(const float4*)(Abase + (size_t)arow * INNER + (kt + 1) * 16 + aq * 4);
            bv = *(const float4*)(Bbase + (size_t)arow * INNER + (kt + 1) * 16 + aq * 4);
        }
#pragma unroll
        for (int kk = 0; kk < 16; kk++) {
            float4 a = *(const float4*)&As[0][kk][ty * 4];
            float4 b = *(const float4*)&Bs[0][kk][tx * 4];
            MICRO_FMA2(acc2, a, b)
        }
        if (kt + 1 < 32) {
            As[1][aq * 4 + 0][arow] = av.x; As[1][aq * 4 + 1][arow] = av.y;
            As[1][aq * 4 + 2][arow] = av.z; As[1][aq * 4 + 3][arow] = av.w;
            Bs[1][aq * 4 + 0][arow] = bv.x; Bs[1][aq * 4 + 1][arow] = bv.y;
            Bs[1][aq * 4 + 2][arow] = bv.z; Bs[1][aq * 4 + 3][arow] = bv.w;
        }
        __syncthreads();
        if (kt + 1 < 32) {
            if (kt + 2 < 32) {
                av = *(const float4*)(Abase + (size_t)arow * INNER + (kt + 2) * 16 + aq * 4);
                bv = *(const float4*)(Bbase + (size_t)arow * INNER + (kt + 2) * 16 + aq * 4);
            }
#pragma unroll
            for (int kk = 0; kk < 16; kk++) {
                float4 a = *(const float4*)&As[1][kk][ty * 4];
                float4 b = *(const float4*)&Bs[1][kk][tx * 4];
                MICRO_FMA2(acc2, a, b)
            }
            if (kt + 2 < 32) {
                As[0][aq * 4 + 0][arow] = av.x; As[0][aq * 4 + 1][arow] = av.y;
                As[0][aq * 4 + 2][arow] = av.z; As[0][aq * 4 + 3][arow] = av.w;
                Bs[0][aq * 4 + 0][arow] = bv.x; Bs[0][aq * 4 + 1][arow] = bv.y;
                Bs[0][aq * 4 + 2][arow] = bv.z; Bs[0][aq * 4 + 3][arow] = bv.w;
            }
            __syncthreads();
        }
    }

    float acc[4][4];
    UNPACK_ACC(acc2, acc)
    int m0 = blockIdx.y * 64 + ty * 4;
    int n0 = blockIdx.x * 64 + tx * 4;
#pragma unroll
    for (int i = 0; i < 4; i++) {
        float4 o = make_float4(acc[i][0] + bp[n0 + 0], acc[i][1] + bp[n0 + 1],
                               acc[i][2] + bp[n0 + 2], acc[i][3] + bp[n0 + 3]);
        *(float4*)&out[(size_t)(m0 + i) * Cc + n0] = o;
    }
}

extern "C" void kernel_launch(void* const* d_in, const int* in_sizes, int n_in,
                              void* d_out, int out_size) {
    const float* x      = (const float*)d_in[0];
    const float* w_qkv  = (const float*)d_in[1];
    const float* w_proj = (const float*)d_in[2];
    const float* b_proj = (const float*)d_in[3];
    const float* w_e    = (const float*)d_in[4];
    const float* b_e    = (const float*)d_in[5];
    const float* w_s    = (const float*)d_in[6];
    const float* b_s    = (const float*)d_in[7];
    const float* w_h    = (const float*)d_in[8];
    const float* b_h    = (const float*)d_in[9];
    const float* alpha  = (const float*)d_in[10];
    const float* beta   = (const float*)d_in[11];
    const float* gamma  = (const float*)d_in[12];
    const float* temp   = (const float*)d_in[13];
    float* out = (float*)d_out;

    k_qkv<<<dim3(24, 64), 256>>>(x, w_qkv);
    k_embed<<<dim3(BH * Nn / 4, 2), 256>>>(w_e, b_e, w_s, b_s, w_h, b_h);
    k_score<<<dim3(16, 16, BH), 256>>>(alpha, beta, gamma, temp);
    k_softmax<<<BH * Nn, 256>>>();
    k_av<<<dim3(16, BH), 256>>>();
    k_proj<<<dim3(8, 64), 256>>>(w_proj, b_proj, out);
}